// round 16
// baseline (speedup 1.0000x reference)
#include <cuda_runtime.h>

// ---------------------------------------------------------------------------
// PCritical step, B=32, N=4096 — fully fused: per-block neuron precompute
// (phase 0) + single pass over W (256x256 tile, four 128x128 subtiles) +
// smem-accumulated accT partials. Epilogue: 2 threads/element shfl-combined
// partial reduction + state update.
// Outputs concatenated float32 in reference return order:
//   S (B,N) | mem_pot_n (B,N) | W_new (N,N) | mem_cur_n (B,N) |
//   mem_pot_p_n (B,N) | mem_cur_p_n (B,N) | refrac_new (B,N)
// ---------------------------------------------------------------------------

#define Bsz 32
#define Nsz 4096
#define BN  (Bsz * Nsz)        // 131072
#define NN  (Nsz * Nsz)        // 16777216

#define C_ALPHA 0.025f
#define C_BETA  0.00025f
#define C_TNOW  10.0f
#define C_INV_TAU_V 0.9801986733067553f
#define C_INV_TAU_I 0.36787944117144233f

#define OUT_S    ((long long)0)
#define OUT_POT  ((long long)BN)
#define OUT_W    ((long long)(2LL * BN))
#define OUT_CUR  ((long long)(2LL * BN + NN))
#define OUT_POTP ((long long)(3LL * BN + NN))
#define OUT_CURP ((long long)(4LL * BN + NN))
#define OUT_REFR ((long long)(5LL * BN + NN))

#define ICH   16               // 4096 / 256 row chunks   (grid.y)
#define JCH   16               // 4096 / 256 col chunks   (grid.x)
#define PITCH 129              // 129 ≡ 1 (mod 32): rows AND cols conflict-free

// scratch (no dynamic allocation allowed)
__device__ __align__(16) float g_accP[ICH * BN];   // partials S@W_new
__device__ __align__(16) float g_accTP[JCH * BN];  // partials S@W_new^T

__device__ __forceinline__ float upd1(float w, float A, float Ai, float e, float ie)
{
    float sub = fmaxf(A * ie, Ai * e);        // 0 when row not paired-spiking
    float u = (w + C_BETA) - sub;
    u = fminf(fmaxf(u, 0.0f), 1.0f);
    return (w > 0.0f) ? u : w;                // sign_mask = W_rec > 0
}

// ---------------------------------------------------------------------------
// K1 (fused): phase 0 computes this block's row/col neuron data in smem,
// then the proven 256x256 tile pass: four 128x128 subtiles in (sj,si) order.
// Phase-B accumulators in registers per j-half; phase-C accumulators in smem
// across j-halves. 512 threads, 2 blocks/SM, 256 blocks.
// ---------------------------------------------------------------------------
__global__ void __launch_bounds__(512, 2) k_fused(
    const float* __restrict__ W, float* __restrict__ Wout,
    const float* __restrict__ mem_pot,
    const float* __restrict__ mem_pot_paired,
    const float* __restrict__ st)
{
    extern __shared__ float sm[];
    float*    c    = sm;                                 // [128][129]
    float*    cacc = sm + 128 * PITCH;                   // [32][256] accT acc
    float*    sA   = cacc + 32 * 256;                    // [256] row A
    float*    sAi  = sA + 256;                           // [256] row Ai
    float*    se   = sAi + 256;                          // [256] col e
    float*    sie  = se + 256;                           // [256] col ie
    unsigned* rbi  = (unsigned*)(sie + 256);             // [32][8] row words
    unsigned* rbj  = rbi + 256;                          // [32][8] col words

    const int jc   = blockIdx.x;       // 0..15
    const int ic   = blockIdx.y;       // 0..15
    const int tid  = threadIdx.x;
    const int warp = tid >> 5;         // 0..15
    const int lane = tid & 31;
    const int jg0  = jc * 256;
    const int igB  = ic * 256;
    const int lp   = lane * PITCH;

    // zero accT smem accumulators
    for (int k = tid; k < 32 * 256; k += 512) cacc[k] = 0.0f;

    // ---- Phase 0: per-neuron precompute for this block's rows and cols ----
    {
        const bool isRow = tid < 256;
        const int  loc   = isRow ? tid : (tid - 256);
        const int  n     = (isRow ? igB : jg0) + loc;

        unsigned m = 0u;
        bool anyp = false;
#pragma unroll
        for (int b = 0; b < 32; ++b) {
            float mp = mem_pot[b * Nsz + n];
            if (mp > 1.0f) m |= (1u << b);
            float mpp = mem_pot_paired[b * Nsz + n];
            if (((mpp - 1.0f) - C_ALPHA) > 0.0f) anyp = true;
        }
        float stn = st[n];
        float maxst = (m == 0xffffffffu) ? C_TNOW
                    : (m ? fmaxf(C_TNOW, stn) : stn);
        float e  = expf(maxst * (1.0f / 50.0f));
        float ie = expf(-maxst * (1.0f / 50.0f));
        if (isRow) {
            sA[loc]  = anyp ? C_ALPHA * e  : 0.0f;
            sAi[loc] = anyp ? C_ALPHA * ie : 0.0f;
        } else {
            se[loc]  = e;
            sie[loc] = ie;
        }
        // transposed masks: warp g<8 -> row group g; warp 8+g -> col group g
        int g = warp & 7;
        unsigned* dst = (warp < 8) ? rbi : rbj;
#pragma unroll
        for (int b = 0; b < 32; ++b) {
            unsigned w = __ballot_sync(0xffffffffu, (m >> b) & 1u);
            if (lane == b) dst[b * 8 + g] = w;
        }
    }
    __syncthreads();   // phase-0 smem visible to all

    // Phase-B accumulators for the current j-half
    float aJ0, aJ1, aJ2, aJ3, bJ0, bJ1, bJ2, bJ3;

#pragma unroll
    for (int sj = 0; sj < 2; ++sj) {
        const int jg = jg0 + sj * 128;
        const int jl0 = sj * 128;

        // per-column exp factors for this j-half (from smem)
        float e0  = se[jl0 + lane];       float ie0 = sie[jl0 + lane];
        float e1  = se[jl0 + lane + 32];  float ie1 = sie[jl0 + lane + 32];
        float e2  = se[jl0 + lane + 64];  float ie2 = sie[jl0 + lane + 64];
        float e3  = se[jl0 + lane + 96];  float ie3 = sie[jl0 + lane + 96];

        aJ0 = aJ1 = aJ2 = aJ3 = 0.0f;
        bJ0 = bJ1 = bJ2 = bJ3 = 0.0f;

#pragma unroll
        for (int si = 0; si < 2; ++si) {
            const int ig0 = igB + si * 128;
            if (sj | si) __syncthreads();   // previous subtile fully consumed

            // ---- Phase A: update 8 contiguous rows per warp ----
#pragma unroll
            for (int r = 0; r < 8; ++r) {
                int il = warp * 8 + r;
                int ig = ig0 + il;
                float A  = sA[si * 128 + il];
                float Ai = sAi[si * 128 + il];
                const float* wr = W    + (size_t)ig * Nsz + jg;
                float*       wo = Wout + (size_t)ig * Nsz + jg;
                float w0 = wr[lane];
                float w1 = wr[lane + 32];
                float w2 = wr[lane + 64];
                float w3 = wr[lane + 96];
                float u0 = upd1(w0, A, Ai, e0, ie0);
                float u1 = upd1(w1, A, Ai, e1, ie1);
                float u2 = upd1(w2, A, Ai, e2, ie2);
                float u3 = upd1(w3, A, Ai, e3, ie3);
                wo[lane]      = u0;
                wo[lane + 32] = u1;
                wo[lane + 64] = u2;
                wo[lane + 96] = u3;
                float* cr = c + il * PITCH;
                cr[lane]      = u0;
                cr[lane + 32] = u1;
                cr[lane + 64] = u2;
                cr[lane + 96] = u3;
            }
            __syncthreads();

            // ---- Phase B: acc[b][j] over active rows (uniform ffs loop) ----
#pragma unroll
            for (int q = 0; q < 4; ++q) {
                unsigned m = rbi[warp * 8 + si * 4 + q];
                while (m) {
                    int r = q * 32 + __ffs(m) - 1; m &= m - 1;
                    const float* cr = c + r * PITCH;
                    aJ0 += cr[lane];
                    aJ1 += cr[lane + 32];
                    aJ2 += cr[lane + 64];
                    aJ3 += cr[lane + 96];
                }
            }
#pragma unroll
            for (int q = 0; q < 4; ++q) {
                unsigned m = rbi[(warp + 16) * 8 + si * 4 + q];
                while (m) {
                    int r = q * 32 + __ffs(m) - 1; m &= m - 1;
                    const float* cr = c + r * PITCH;
                    bJ0 += cr[lane];
                    bJ1 += cr[lane + 32];
                    bJ2 += cr[lane + 64];
                    bJ3 += cr[lane + 96];
                }
            }

            // ---- Phase C: accT[b][i] over active cols -> smem accumulator ----
            {
                float aI0 = 0, aI1 = 0, aI2 = 0, aI3 = 0;
                float bI0 = 0, bI1 = 0, bI2 = 0, bI3 = 0;
#pragma unroll
                for (int q = 0; q < 4; ++q) {
                    unsigned m = rbj[warp * 8 + sj * 4 + q];
                    while (m) {
                        int j = q * 32 + __ffs(m) - 1; m &= m - 1;
                        const float* cc = c + j + lp;
                        aI0 += cc[0];
                        aI1 += cc[32 * PITCH];
                        aI2 += cc[64 * PITCH];
                        aI3 += cc[96 * PITCH];
                    }
                }
#pragma unroll
                for (int q = 0; q < 4; ++q) {
                    unsigned m = rbj[(warp + 16) * 8 + sj * 4 + q];
                    while (m) {
                        int j = q * 32 + __ffs(m) - 1; m &= m - 1;
                        const float* cc = c + j + lp;
                        bI0 += cc[0];
                        bI1 += cc[32 * PITCH];
                        bI2 += cc[64 * PITCH];
                        bI3 += cc[96 * PITCH];
                    }
                }
                // fold into smem accT accumulator (warp-private rows, no races)
                float* pa = cacc + warp * 256 + si * 128 + lane;
                pa[0]  += aI0;
                pa[32] += aI1;
                pa[64] += aI2;
                pa[96] += aI3;
                float* pb = cacc + (warp + 16) * 256 + si * 128 + lane;
                pb[0]  += bI0;
                pb[32] += bI1;
                pb[64] += bI2;
                pb[96] += bI3;
            }
        }

        // write Phase-B partials for this j-half (one per ic chunk)
        {
            size_t oa = ((size_t)ic * Bsz + warp) * Nsz + jg + lane;
            g_accP[oa]      = aJ0;
            g_accP[oa + 32] = aJ1;
            g_accP[oa + 64] = aJ2;
            g_accP[oa + 96] = aJ3;
            size_t ob = ((size_t)ic * Bsz + warp + 16) * Nsz + jg + lane;
            g_accP[ob]      = bJ0;
            g_accP[ob + 32] = bJ1;
            g_accP[ob + 64] = bJ2;
            g_accP[ob + 96] = bJ3;
        }
    }

    // dump smem accT accumulator -> g_accTP[jc][b][igB + il]  (coalesced)
    __syncthreads();
#pragma unroll
    for (int k = 0; k < 16; ++k) {
        int idx = tid + 512 * k;          // 0..8191
        int b   = idx >> 8;
        int il  = idx & 255;
        g_accTP[((size_t)jc * Bsz + b) * Nsz + igB + il] = cacc[b * 256 + il];
    }
}

// ---------------------------------------------------------------------------
// K2: epilogue — 2 threads per element (even lane: chunks 0-7, odd lane:
// chunks 8-15), shfl_xor combine, both compute state, each writes 3 outputs.
// 262144 threads -> ~86% occupancy, 16-load chains.
// ---------------------------------------------------------------------------
__global__ void __launch_bounds__(256) k_epilogue(
    const float* __restrict__ inp,
    const float* __restrict__ mem_pot,
    const float* __restrict__ mem_cur,
    const float* __restrict__ mem_pot_paired,
    const float* __restrict__ mem_cur_paired,
    const int*   __restrict__ refrac,
    float* __restrict__ out)
{
    const int gid  = blockIdx.x * 256 + threadIdx.x;   // 2*BN threads
    const int t    = gid >> 1;                         // element id
    const int half = gid & 1;

    float pa = 0.0f, pt = 0.0f;
#pragma unroll
    for (int k = 0; k < 8; ++k) {
        pa += g_accP [(size_t)(half * 8 + k) * BN + t];
        pt += g_accTP[(size_t)(half * 8 + k) * BN + t];
    }
    float oa = __shfl_xor_sync(0xffffffffu, pa, 1);
    float ot = __shfl_xor_sync(0xffffffffu, pt, 1);
    // deterministic: always (chunks 0-7) + (chunks 8-15)
    float acc  = half ? (oa + pa) : (pa + oa);
    float accT = half ? (ot + pt) : (pt + ot);

    int r  = refrac[t];
    int rd = (r > 0) ? (r - 1) : r;
    bool active = (rd == 0);

    float mp   = mem_pot[t];
    bool  s    = mp > 1.0f;                   // S = clip(ceil(mp-1),0,1)
    float mppv = mem_pot_paired[t];
    bool  sp   = ((mppv - 1.0f) - C_ALPHA) > 0.0f;

    float mc   = mem_cur[t];
    float mcpv = mem_cur_paired[t];

    float mcn  = active ? (inp[t] + acc) + mc : mc;
    float mcpn = active ? accT + mcpv : mcpv;
    float mpn  = active ? mcn + mp : mp;
    float mppn = active ? mcpn + mppv : mppv;

    mpn  *= C_INV_TAU_V;
    mcn  *= C_INV_TAU_I;
    mppn *= C_INV_TAU_V;
    mcpn *= C_INV_TAU_I;

    if (s)  mpn  = 0.0f;
    if (sp) mppn = 0.0f;

    if (half == 0) {
        out[OUT_S    + t] = s ? 1.0f : 0.0f;
        out[OUT_POT  + t] = mpn;
        out[OUT_CUR  + t] = mcn;
    } else {
        out[OUT_POTP + t] = mppn;
        out[OUT_CURP + t] = mcpn;
        out[OUT_REFR + t] = s ? 2.0f : (float)rd;
    }
}

// ---------------------------------------------------------------------------
extern "C" void kernel_launch(void* const* d_in, const int* in_sizes, int n_in,
                              void* d_out, int out_size)
{
    const float* inp      = (const float*)d_in[0];
    const float* W_rec    = (const float*)d_in[1];
    const float* mem_pot  = (const float*)d_in[2];
    const float* mem_cur  = (const float*)d_in[3];
    const float* mpp      = (const float*)d_in[4];
    const float* mcp      = (const float*)d_in[5];
    const float* st       = (const float*)d_in[6];
    const int*   refrac   = (const int*)d_in[7];
    float* out = (float*)d_out;
    float* Wout = out + OUT_W;

    const int smem_bytes = (128 * PITCH + 32 * 256 + 4 * 256 + 512) * 4; // ~104.5 KB
    cudaFuncSetAttribute(k_fused, cudaFuncAttributeMaxDynamicSharedMemorySize,
                         smem_bytes);

    k_fused<<<dim3(JCH, ICH), 512, smem_bytes>>>(W_rec, Wout, mem_pot, mpp, st);
    k_epilogue<<<2 * BN / 256, 256>>>(inp, mem_pot, mem_cur, mpp, mcp, refrac, out);
}

// round 17
// speedup vs baseline: 1.4260x; 1.4260x over previous
#include <cuda_runtime.h>

// ---------------------------------------------------------------------------
// PCritical step, B=32, N=4096 — fully fused: per-block neuron precompute
// (phase 0) + single pass over W (256x256 tile, four 128x128 subtiles) +
// smem-accumulated accT partials. Separate epilogue reduces partials
// (dual-chain ILP, deterministic fixed-order combine).
// Outputs concatenated float32 in reference return order:
//   S (B,N) | mem_pot_n (B,N) | W_new (N,N) | mem_cur_n (B,N) |
//   mem_pot_p_n (B,N) | mem_cur_p_n (B,N) | refrac_new (B,N)
// ---------------------------------------------------------------------------

#define Bsz 32
#define Nsz 4096
#define BN  (Bsz * Nsz)        // 131072
#define NN  (Nsz * Nsz)        // 16777216

#define C_ALPHA 0.025f
#define C_BETA  0.00025f
#define C_TNOW  10.0f
#define C_INV_TAU_V 0.9801986733067553f
#define C_INV_TAU_I 0.36787944117144233f

#define OUT_S    ((long long)0)
#define OUT_POT  ((long long)BN)
#define OUT_W    ((long long)(2LL * BN))
#define OUT_CUR  ((long long)(2LL * BN + NN))
#define OUT_POTP ((long long)(3LL * BN + NN))
#define OUT_CURP ((long long)(4LL * BN + NN))
#define OUT_REFR ((long long)(5LL * BN + NN))

#define ICH   16               // 4096 / 256 row chunks   (grid.y)
#define JCH   16               // 4096 / 256 col chunks   (grid.x)
#define PITCH 129              // 129 ≡ 1 (mod 32): rows AND cols conflict-free

// scratch (no dynamic allocation allowed)
__device__ __align__(16) float g_accP[ICH * BN];   // partials S@W_new
__device__ __align__(16) float g_accTP[JCH * BN];  // partials S@W_new^T

__device__ __forceinline__ float upd1(float w, float A, float Ai, float e, float ie)
{
    float sub = fmaxf(A * ie, Ai * e);        // 0 when row not paired-spiking
    float u = (w + C_BETA) - sub;
    u = fminf(fmaxf(u, 0.0f), 1.0f);
    return (w > 0.0f) ? u : w;                // sign_mask = W_rec > 0
}

// ---------------------------------------------------------------------------
// K1 (fused): phase 0 computes this block's row/col neuron data in smem,
// then the proven 256x256 tile pass: four 128x128 subtiles in (sj,si) order.
// Phase-B accumulators in registers per j-half; phase-C accumulators in smem
// across j-halves. 512 threads, 2 blocks/SM, 256 blocks.
// ---------------------------------------------------------------------------
__global__ void __launch_bounds__(512, 2) k_fused(
    const float* __restrict__ W, float* __restrict__ Wout,
    const float* __restrict__ mem_pot,
    const float* __restrict__ mem_pot_paired,
    const float* __restrict__ st)
{
    extern __shared__ float sm[];
    float*    c    = sm;                                 // [128][129]
    float*    cacc = sm + 128 * PITCH;                   // [32][256] accT acc
    float*    sA   = cacc + 32 * 256;                    // [256] row A
    float*    sAi  = sA + 256;                           // [256] row Ai
    float*    se   = sAi + 256;                          // [256] col e
    float*    sie  = se + 256;                           // [256] col ie
    unsigned* rbi  = (unsigned*)(sie + 256);             // [32][8] row words
    unsigned* rbj  = rbi + 256;                          // [32][8] col words

    const int jc   = blockIdx.x;       // 0..15
    const int ic   = blockIdx.y;       // 0..15
    const int tid  = threadIdx.x;
    const int warp = tid >> 5;         // 0..15
    const int lane = tid & 31;
    const int jg0  = jc * 256;
    const int igB  = ic * 256;
    const int lp   = lane * PITCH;

    // zero accT smem accumulators
    for (int k = tid; k < 32 * 256; k += 512) cacc[k] = 0.0f;

    // ---- Phase 0: per-neuron precompute for this block's rows and cols ----
    {
        const bool isRow = tid < 256;
        const int  loc   = isRow ? tid : (tid - 256);
        const int  n     = (isRow ? igB : jg0) + loc;

        unsigned m = 0u;
        bool anyp = false;
#pragma unroll
        for (int b = 0; b < 32; ++b) {
            float mp = mem_pot[b * Nsz + n];
            if (mp > 1.0f) m |= (1u << b);
            float mpp = mem_pot_paired[b * Nsz + n];
            if (((mpp - 1.0f) - C_ALPHA) > 0.0f) anyp = true;
        }
        float stn = st[n];
        float maxst = (m == 0xffffffffu) ? C_TNOW
                    : (m ? fmaxf(C_TNOW, stn) : stn);
        float e  = expf(maxst * (1.0f / 50.0f));
        float ie = expf(-maxst * (1.0f / 50.0f));
        if (isRow) {
            sA[loc]  = anyp ? C_ALPHA * e  : 0.0f;
            sAi[loc] = anyp ? C_ALPHA * ie : 0.0f;
        } else {
            se[loc]  = e;
            sie[loc] = ie;
        }
        // transposed masks: warp g<8 -> row group g; warp 8+g -> col group g
        int g = warp & 7;
        unsigned* dst = (warp < 8) ? rbi : rbj;
#pragma unroll
        for (int b = 0; b < 32; ++b) {
            unsigned w = __ballot_sync(0xffffffffu, (m >> b) & 1u);
            if (lane == b) dst[b * 8 + g] = w;
        }
    }
    __syncthreads();   // phase-0 smem visible to all

    // Phase-B accumulators for the current j-half
    float aJ0, aJ1, aJ2, aJ3, bJ0, bJ1, bJ2, bJ3;

#pragma unroll
    for (int sj = 0; sj < 2; ++sj) {
        const int jg = jg0 + sj * 128;
        const int jl0 = sj * 128;

        // per-column exp factors for this j-half (from smem)
        float e0  = se[jl0 + lane];       float ie0 = sie[jl0 + lane];
        float e1  = se[jl0 + lane + 32];  float ie1 = sie[jl0 + lane + 32];
        float e2  = se[jl0 + lane + 64];  float ie2 = sie[jl0 + lane + 64];
        float e3  = se[jl0 + lane + 96];  float ie3 = sie[jl0 + lane + 96];

        aJ0 = aJ1 = aJ2 = aJ3 = 0.0f;
        bJ0 = bJ1 = bJ2 = bJ3 = 0.0f;

#pragma unroll
        for (int si = 0; si < 2; ++si) {
            const int ig0 = igB + si * 128;
            if (sj | si) __syncthreads();   // previous subtile fully consumed

            // ---- Phase A: update 8 contiguous rows per warp ----
#pragma unroll
            for (int r = 0; r < 8; ++r) {
                int il = warp * 8 + r;
                int ig = ig0 + il;
                float A  = sA[si * 128 + il];
                float Ai = sAi[si * 128 + il];
                const float* wr = W    + (size_t)ig * Nsz + jg;
                float*       wo = Wout + (size_t)ig * Nsz + jg;
                float w0 = wr[lane];
                float w1 = wr[lane + 32];
                float w2 = wr[lane + 64];
                float w3 = wr[lane + 96];
                float u0 = upd1(w0, A, Ai, e0, ie0);
                float u1 = upd1(w1, A, Ai, e1, ie1);
                float u2 = upd1(w2, A, Ai, e2, ie2);
                float u3 = upd1(w3, A, Ai, e3, ie3);
                wo[lane]      = u0;
                wo[lane + 32] = u1;
                wo[lane + 64] = u2;
                wo[lane + 96] = u3;
                float* cr = c + il * PITCH;
                cr[lane]      = u0;
                cr[lane + 32] = u1;
                cr[lane + 64] = u2;
                cr[lane + 96] = u3;
            }
            __syncthreads();

            // ---- Phase B: acc[b][j] over active rows (uniform ffs loop) ----
#pragma unroll
            for (int q = 0; q < 4; ++q) {
                unsigned m = rbi[warp * 8 + si * 4 + q];
                while (m) {
                    int r = q * 32 + __ffs(m) - 1; m &= m - 1;
                    const float* cr = c + r * PITCH;
                    aJ0 += cr[lane];
                    aJ1 += cr[lane + 32];
                    aJ2 += cr[lane + 64];
                    aJ3 += cr[lane + 96];
                }
            }
#pragma unroll
            for (int q = 0; q < 4; ++q) {
                unsigned m = rbi[(warp + 16) * 8 + si * 4 + q];
                while (m) {
                    int r = q * 32 + __ffs(m) - 1; m &= m - 1;
                    const float* cr = c + r * PITCH;
                    bJ0 += cr[lane];
                    bJ1 += cr[lane + 32];
                    bJ2 += cr[lane + 64];
                    bJ3 += cr[lane + 96];
                }
            }

            // ---- Phase C: accT[b][i] over active cols -> smem accumulator ----
            {
                float aI0 = 0, aI1 = 0, aI2 = 0, aI3 = 0;
                float bI0 = 0, bI1 = 0, bI2 = 0, bI3 = 0;
#pragma unroll
                for (int q = 0; q < 4; ++q) {
                    unsigned m = rbj[warp * 8 + sj * 4 + q];
                    while (m) {
                        int j = q * 32 + __ffs(m) - 1; m &= m - 1;
                        const float* cc = c + j + lp;
                        aI0 += cc[0];
                        aI1 += cc[32 * PITCH];
                        aI2 += cc[64 * PITCH];
                        aI3 += cc[96 * PITCH];
                    }
                }
#pragma unroll
                for (int q = 0; q < 4; ++q) {
                    unsigned m = rbj[(warp + 16) * 8 + sj * 4 + q];
                    while (m) {
                        int j = q * 32 + __ffs(m) - 1; m &= m - 1;
                        const float* cc = c + j + lp;
                        bI0 += cc[0];
                        bI1 += cc[32 * PITCH];
                        bI2 += cc[64 * PITCH];
                        bI3 += cc[96 * PITCH];
                    }
                }
                // fold into smem accT accumulator (warp-private rows, no races)
                float* pa = cacc + warp * 256 + si * 128 + lane;
                pa[0]  += aI0;
                pa[32] += aI1;
                pa[64] += aI2;
                pa[96] += aI3;
                float* pb = cacc + (warp + 16) * 256 + si * 128 + lane;
                pb[0]  += bI0;
                pb[32] += bI1;
                pb[64] += bI2;
                pb[96] += bI3;
            }
        }

        // write Phase-B partials for this j-half (one per ic chunk)
        {
            size_t oa = ((size_t)ic * Bsz + warp) * Nsz + jg + lane;
            g_accP[oa]      = aJ0;
            g_accP[oa + 32] = aJ1;
            g_accP[oa + 64] = aJ2;
            g_accP[oa + 96] = aJ3;
            size_t ob = ((size_t)ic * Bsz + warp + 16) * Nsz + jg + lane;
            g_accP[ob]      = bJ0;
            g_accP[ob + 32] = bJ1;
            g_accP[ob + 64] = bJ2;
            g_accP[ob + 96] = bJ3;
        }
    }

    // dump smem accT accumulator -> g_accTP[jc][b][igB + il]  (coalesced)
    __syncthreads();
#pragma unroll
    for (int k = 0; k < 16; ++k) {
        int idx = tid + 512 * k;          // 0..8191
        int b   = idx >> 8;
        int il  = idx & 255;
        g_accTP[((size_t)jc * Bsz + b) * Nsz + igB + il] = cacc[b * 256 + il];
    }
}

// ---------------------------------------------------------------------------
// K2: epilogue — reduce partials (dual-chain ILP, fixed combine order),
// integrate, leak, reset, refractory. 512 blocks x 256 threads (R12 shape).
// ---------------------------------------------------------------------------
__global__ void __launch_bounds__(256) k_epilogue(
    const float* __restrict__ inp,
    const float* __restrict__ mem_pot,
    const float* __restrict__ mem_cur,
    const float* __restrict__ mem_pot_paired,
    const float* __restrict__ mem_cur_paired,
    const int*   __restrict__ refrac,
    float* __restrict__ out)
{
    int t = blockIdx.x * 256 + threadIdx.x;   // BN threads

    // dual independent chains (deterministic: fixed grouping + fixed combine)
    float accA = 0.0f, accB = 0.0f;
#pragma unroll
    for (int cN = 0; cN < 8; ++cN) {
        accA += g_accP[(size_t)cN * BN + t];
        accB += g_accP[(size_t)(cN + 8) * BN + t];
    }
    float acc = accA + accB;

    float atA = 0.0f, atB = 0.0f;
#pragma unroll
    for (int cN = 0; cN < 8; ++cN) {
        atA += g_accTP[(size_t)cN * BN + t];
        atB += g_accTP[(size_t)(cN + 8) * BN + t];
    }
    float accT = atA + atB;

    int r  = refrac[t];
    int rd = (r > 0) ? (r - 1) : r;
    bool active = (rd == 0);

    float mp   = mem_pot[t];
    bool  s    = mp > 1.0f;                   // S = clip(ceil(mp-1),0,1)
    float mppv = mem_pot_paired[t];
    bool  sp   = ((mppv - 1.0f) - C_ALPHA) > 0.0f;

    float mc   = mem_cur[t];
    float mcpv = mem_cur_paired[t];

    float mcn  = active ? (inp[t] + acc) + mc : mc;
    float mcpn = active ? accT + mcpv : mcpv;
    float mpn  = active ? mcn + mp : mp;
    float mppn = active ? mcpn + mppv : mppv;

    mpn  *= C_INV_TAU_V;
    mcn  *= C_INV_TAU_I;
    mppn *= C_INV_TAU_V;
    mcpn *= C_INV_TAU_I;

    if (s)  mpn  = 0.0f;
    if (sp) mppn = 0.0f;
    float rn = s ? 2.0f : (float)rd;

    out[OUT_S    + t] = s ? 1.0f : 0.0f;
    out[OUT_POT  + t] = mpn;
    out[OUT_CUR  + t] = mcn;
    out[OUT_POTP + t] = mppn;
    out[OUT_CURP + t] = mcpn;
    out[OUT_REFR + t] = rn;
}

// ---------------------------------------------------------------------------
extern "C" void kernel_launch(void* const* d_in, const int* in_sizes, int n_in,
                              void* d_out, int out_size)
{
    const float* inp      = (const float*)d_in[0];
    const float* W_rec    = (const float*)d_in[1];
    const float* mem_pot  = (const float*)d_in[2];
    const float* mem_cur  = (const float*)d_in[3];
    const float* mpp      = (const float*)d_in[4];
    const float* mcp      = (const float*)d_in[5];
    const float* st       = (const float*)d_in[6];
    const int*   refrac   = (const int*)d_in[7];
    float* out = (float*)d_out;
    float* Wout = out + OUT_W;

    const int smem_bytes = (128 * PITCH + 32 * 256 + 4 * 256 + 512) * 4; // ~104.5 KB
    cudaFuncSetAttribute(k_fused, cudaFuncAttributeMaxDynamicSharedMemorySize,
                         smem_bytes);

    k_fused<<<dim3(JCH, ICH), 512, smem_bytes>>>(W_rec, Wout, mem_pot, mpp, st);
    k_epilogue<<<BN / 256, 256>>>(inp, mem_pot, mem_cur, mpp, mcp, refrac, out);
}